// round 11
// baseline (speedup 1.0000x reference)
#include <cuda_runtime.h>
#include <math.h>

// Problem dims (fixed by the reference setup)
#define NB 4096
#define NT 512
#define NS 6
#define NF 12
#define NW (NB / 32)          // 128 batch-groups

__device__ unsigned g_bp[NW * NT * 32];   // packed backpointers [w][t][lane]

// SMEM ring geometry
#define SLICE_W  194          // padded slice row (words); even -> float2-aligned
#define CHUNK_T  32
#define RING_CH  8
#define CHUNK_W  (CHUNK_T * SLICE_W)
#define N_CHUNKS (NT / CHUNK_T)              // 16
#define RING_BYTES (RING_CH * CHUNK_W * 4)   // 198656 B

// One DP step: read e(t) from ring at P, update v in registers, overwrite the
// slice with v_t. Numerical order identical to R6-R10.
#define DP_STEP(P) do {                                                       \
    const float2* q_ = (const float2*)(P);                                    \
    float2 a_ = q_[0], b_ = q_[1], c_ = q_[2];                                \
    float e0=a_.x, e1=a_.y, e2=b_.x, e3=b_.y, e4=c_.x, e5=c_.y;               \
    float n0 = fmaxf(fmaxf(fmaxf(v[0]+lt[0],  v[1]+lt[6]),                    \
                           fmaxf(v[2]+lt[12], v[3]+lt[18])),                  \
                     fmaxf(v[4]+lt[24], v[5]+lt[30])) + e0;                   \
    float n1 = fmaxf(fmaxf(fmaxf(v[0]+lt[1],  v[1]+lt[7]),                    \
                           fmaxf(v[2]+lt[13], v[3]+lt[19])),                  \
                     fmaxf(v[4]+lt[25], v[5]+lt[31])) + e1;                   \
    float n2 = fmaxf(fmaxf(fmaxf(v[0]+lt[2],  v[1]+lt[8]),                    \
                           fmaxf(v[2]+lt[14], v[3]+lt[20])),                  \
                     fmaxf(v[4]+lt[26], v[5]+lt[32])) + e2;                   \
    float n3 = fmaxf(fmaxf(fmaxf(v[0]+lt[3],  v[1]+lt[9]),                    \
                           fmaxf(v[2]+lt[15], v[3]+lt[21])),                  \
                     fmaxf(v[4]+lt[27], v[5]+lt[33])) + e3;                   \
    float n4 = fmaxf(fmaxf(fmaxf(v[0]+lt[4],  v[1]+lt[10]),                   \
                           fmaxf(v[2]+lt[16], v[3]+lt[22])),                  \
                     fmaxf(v[4]+lt[28], v[5]+lt[34])) + e4;                   \
    float n5 = fmaxf(fmaxf(fmaxf(v[0]+lt[5],  v[1]+lt[11]),                   \
                           fmaxf(v[2]+lt[17], v[3]+lt[23])),                  \
                     fmaxf(v[4]+lt[29], v[5]+lt[35])) + e5;                   \
    v[0]=n0; v[1]=n1; v[2]=n2; v[3]=n3; v[4]=n4; v[5]=n5;                     \
    float2* d_ = (float2*)(P);                                                \
    d_[0] = make_float2(v[0], v[1]);                                          \
    d_[1] = make_float2(v[2], v[3]);                                          \
    d_[2] = make_float2(v[4], v[5]); } while (0)

// Backtrace 16-step block (ping-pong register buffers, compile-time indices)
#define BWD_BLOCK16(CUR, NXT, DO_PREF)                                      \
do {                                                                        \
    _Pragma("unroll")                                                       \
    for (int i = 0; i < 16; i++) {                                          \
        if (DO_PREF) NXT[i] = __ldg(bprow + (size_t)(tb - 16 - i) * 32);    \
        itile[lane * 33 + ((tb - i) & 31)] = cur;    /* path[tb - i] */     \
        cur = (CUR[i] >> (cur * 4)) & 7;             /* path[tb - i - 1] */ \
    }                                                                       \
    if (((tb - 15) & 31) == 0) {     /* itile row holds path[tb-15..tb+16] */\
        __syncwarp();                                                       \
        if (write_path) {                                                   \
            _Pragma("unroll 8")                                             \
            for (int r = 0; r < 32; r++)                                    \
                out[(size_t)(b0 + r) * NT + (tb - 15) + lane] =             \
                    (float)itile[r * 33 + lane];                            \
        }                                                                   \
        __syncwarp();                                                       \
    }                                                                       \
    tb -= 16;                                                               \
} while (0)

// ---------------------------------------------------------------------------
// THE kernel. 192 threads (6 warps) per batch-group:
//   init:    all threads compute params (softmax logs, emission consts) in SMEM
//   wid 0-2: emission producers (depth-3 software-pipelined obs loads)
//   wid 3:   serial DP consumer (unroll-4 steps; writes v_t into ring in place)
//   wid 4-5: bp workers; read v from ring, write packed bp to gmem
//   tail:    after __syncthreads(), wid 0 runs the backtrace (bp is L2-hot)
// ---------------------------------------------------------------------------
__global__ void __launch_bounds__(192, 1)
k_all(const float* __restrict__ obs,
      const float* __restrict__ trans,
      const float* __restrict__ init,
      const float* __restrict__ means,
      const float* __restrict__ logsc,
      float* __restrict__ out,
      int write_path, int write_score, int score_off)
{
    extern __shared__ float ring[];
    __shared__ float sp[156];          // inv2[72], mu*inv2[72], c[6], logdet[6]
    __shared__ float slt[36];          // log-transition [p][s]
    __shared__ float sloginit[6];
    __shared__ int   prod_cnt[N_CHUNKS];
    __shared__ int   bp_cnt[N_CHUNKS];
    __shared__ int   cons_flag;
    __shared__ int   slast[32];

    int tid  = threadIdx.x;
    int lane = tid & 31;
    int wid  = tid >> 5;
    int w    = blockIdx.x;

    // ---- parameter setup in SMEM (same math as the old k_setup) ----
    if (tid < 36) {
        int p = tid / 6, s = tid - p * 6;
        float m = trans[p * 6 + 0];
#pragma unroll
        for (int k = 1; k < 6; k++) m = fmaxf(m, trans[p * 6 + k]);
        float sum = 0.f;
#pragma unroll
        for (int k = 0; k < 6; k++) sum += expf(trans[p * 6 + k] - m);
        slt[tid] = logf(expf(trans[p * 6 + s] - m) / sum + 1e-8f);
    }
    if (tid >= 36 && tid < 42) {
        int s = tid - 36;
        float m = init[0];
#pragma unroll
        for (int k = 1; k < 6; k++) m = fmaxf(m, init[k]);
        float sum = 0.f;
#pragma unroll
        for (int k = 0; k < 6; k++) sum += expf(init[k] - m);
        sloginit[s] = logf(expf(init[s] - m) / sum + 1e-8f);
    }
    if (tid >= 64 && tid < 136) {
        int idx = tid - 64;
        int s = idx / 12, f = idx - s * 12;
        float x    = logsc[s * 12 + f];
        float sc   = log1pf(expf(x)) + 1e-6f;
        float den  = sc + 1e-6f;
        float inv2 = 1.0f / (den * den);
        float mu   = means[s * 12 + f];
        sp[s * 12 + f]      = inv2;
        sp[72 + s * 12 + f] = mu * inv2;
    }
    if (tid >= 136 && tid < 142) {
        int s = tid - 136;
        float c = 0.f, ld = 0.f;
#pragma unroll
        for (int f = 0; f < 12; f++) {
            float x    = logsc[s * 12 + f];
            float sc   = log1pf(expf(x)) + 1e-6f;
            float den  = sc + 1e-6f;
            float inv2 = 1.0f / (den * den);
            float mu   = means[s * 12 + f];
            c  += mu * mu * inv2;
            ld += logf(sc);
        }
        sp[144 + s] = c;
        sp[150 + s] = ld;
    }
    if (tid < N_CHUNKS) { prod_cnt[tid] = 0; bp_cnt[tid] = 0; }
    if (tid == 0) cons_flag = 0;
    __syncthreads();

    if (wid < 3) {
        // ================= producers (depth-3 pipeline) =================
        const float4* ob4 = (const float4*)(obs + (size_t)w * 32 * NT * NF);
        const int NV = (wid == 2) ? 10 : 11;   // warp-uniform

#pragma unroll 1
        for (int c = 0; c < N_CHUNKS; c++) {
            int t0 = c * CHUNK_T;

            // preload iterations 0..2 (gmem only — issue BEFORE backpressure wait)
            float4 pre[3][3];
#pragma unroll
            for (int k = 0; k < 3; k++) {
                int b_ = wid + 3 * k;
                const float4* op = ob4 + (size_t)(b_ * NT + t0 + lane) * 3;
                pre[k][0] = __ldcs(op); pre[k][1] = __ldcs(op + 1); pre[k][2] = __ldcs(op + 2);
            }

            if (c >= RING_CH) {   // slot (c&7) free iff bp chunk c-7 done
                while (*(volatile int*)&bp_cnt[c - (RING_CH - 1)] < 2) { }
                __threadfence_block();
            }
            float* slot = ring + (size_t)(c & (RING_CH - 1)) * CHUNK_W;

#pragma unroll
            for (int i = 0; i < 11; i++) {
                if (i < NV) {
                    int b_ = wid + 3 * i;
                    float4 q0 = pre[i % 3][0], q1 = pre[i % 3][1], q2 = pre[i % 3][2];
                    if (i + 3 < NV) {
                        int bn = wid + 3 * (i + 3);
                        const float4* op = ob4 + (size_t)(bn * NT + t0 + lane) * 3;
                        pre[i % 3][0] = __ldcs(op);
                        pre[i % 3][1] = __ldcs(op + 1);
                        pre[i % 3][2] = __ldcs(op + 2);
                    }
                    float o[12] = { q0.x, q0.y, q0.z, q0.w, q1.x, q1.y, q1.z, q1.w,
                                    q2.x, q2.y, q2.z, q2.w };
                    float osq[12];
#pragma unroll
                    for (int f = 0; f < 12; f++) osq[f] = o[f] * o[f];
                    float e[6];
#pragma unroll
                    for (int s = 0; s < NS; s++) {
                        float a1 = 0.f, a2 = 0.f;
#pragma unroll
                        for (int f = 0; f < 12; f++) {
                            a1 = fmaf(osq[f], sp[s * 12 + f], a1);
                            a2 = fmaf(o[f],   sp[72 + s * 12 + f], a2);
                        }
                        e[s] = -0.5f * (a1 - 2.f * a2 + sp[144 + s]) - sp[150 + s];
                    }
                    float2* d = (float2*)(slot + lane * SLICE_W + b_ * 6);
                    d[0] = make_float2(e[0], e[1]);
                    d[1] = make_float2(e[2], e[3]);
                    d[2] = make_float2(e[4], e[5]);
                }
            }
            __syncwarp();
            __threadfence_block();
            if (lane == 0) atomicAdd(&prod_cnt[c], 1);
        }
    } else if (wid == 3) {
        // ================= consumer (chunk DP, unroll-4 groups) ============
        float lt[36];
#pragma unroll
        for (int i = 0; i < 36; i++) lt[i] = slt[i];

        float v[6];

        // chunk 0 (peeled: t=0 init + steps 1..3, then 7 groups of 4)
        while (*(volatile int*)&prod_cnt[0] < 3) { }
        __threadfence_block();
        {
            float* bb = ring + lane * 6;
            const float2* q = (const float2*)bb;
            float2 a = q[0], b2 = q[1], c2 = q[2];
            v[0] = sloginit[0] + a.x;  v[1] = sloginit[1] + a.y;
            v[2] = sloginit[2] + b2.x; v[3] = sloginit[3] + b2.y;
            v[4] = sloginit[4] + c2.x; v[5] = sloginit[5] + c2.y;
            float2* d = (float2*)bb;
            d[0] = make_float2(v[0], v[1]);
            d[1] = make_float2(v[2], v[3]);
            d[2] = make_float2(v[4], v[5]);
            DP_STEP(bb + 1 * SLICE_W);
            DP_STEP(bb + 2 * SLICE_W);
            DP_STEP(bb + 3 * SLICE_W);
#pragma unroll 1
            for (int g = 1; g < 8; g++) {
                float* p4 = bb + g * 4 * SLICE_W;
                DP_STEP(p4);
                DP_STEP(p4 + SLICE_W);
                DP_STEP(p4 + 2 * SLICE_W);
                DP_STEP(p4 + 3 * SLICE_W);
            }
        }
        __syncwarp();
        __threadfence_block();
        if (lane == 0) *(volatile int*)&cons_flag = 1;

#pragma unroll 1
        for (int c = 1; c < N_CHUNKS; c++) {
            while (*(volatile int*)&prod_cnt[c] < 3) { }
            __threadfence_block();
            float* bb = ring + (size_t)(c & (RING_CH - 1)) * CHUNK_W + lane * 6;
#pragma unroll 1
            for (int g = 0; g < 8; g++) {
                float* p4 = bb + g * 4 * SLICE_W;
                DP_STEP(p4);
                DP_STEP(p4 + SLICE_W);
                DP_STEP(p4 + 2 * SLICE_W);
                DP_STEP(p4 + 3 * SLICE_W);
            }
            __syncwarp();
            __threadfence_block();
            if (lane == 0) *(volatile int*)&cons_flag = c + 1;
        }

        // final state / score (first-argmax, strict >)
        float m = v[0]; int idx = 0;
#pragma unroll
        for (int s = 1; s < 6; s++) if (v[s] > m) { m = v[s]; idx = s; }
        slast[lane] = idx;
        if (write_score) out[score_off + w * 32 + lane] = m;
    } else {
        // ================= bp workers (wid 4: slices 0-15, wid 5: 16-31) ===
        float lt[36];
#pragma unroll
        for (int i = 0; i < 36; i++) lt[i] = slt[i];

        int half = wid - 4;
        unsigned* bpw = g_bp + (size_t)w * NT * 32 + lane;

#pragma unroll 1
        for (int c = 0; c < N_CHUNKS; c++) {
            while (*(volatile int*)&cons_flag < c + 1) { }
            __threadfence_block();

#pragma unroll 1
            for (int i = 0; i < 16; i++) {
                int t = c * 32 + half * 16 + i;
                if (t == 0) continue;
                int tp = t - 1;
                const float2* q = (const float2*)(ring +
                    (size_t)((tp >> 5) & (RING_CH - 1)) * CHUNK_W +
                    (tp & 31) * SLICE_W + lane * 6);
                float2 a = q[0], bq = q[1], cc = q[2];
                float v0 = a.x, v1 = a.y, v2 = bq.x, v3 = bq.y, v4 = cc.x, v5 = cc.y;

                unsigned pk = 0;
#pragma unroll
                for (int s = 0; s < 6; s++) {
                    float c0 = v0 + lt[s],      c1 = v1 + lt[6 + s],  c2 = v2 + lt[12 + s];
                    float c3 = v3 + lt[18 + s], c4 = v4 + lt[24 + s], c5 = v5 + lt[30 + s];
                    bool g01 = c1 > c0;  float m01 = g01 ? c1 : c0;  int i01 = g01 ? 1 : 0;
                    bool g23 = c3 > c2;  float m23 = g23 ? c3 : c2;  int i23 = g23 ? 3 : 2;
                    bool g45 = c5 > c4;  float m45 = g45 ? c5 : c4;  int i45 = g45 ? 5 : 4;
                    bool gA  = m23 > m01; float mA = gA ? m23 : m01; int iA = gA ? i23 : i01;
                    bool gB  = m45 > mA;  int idx = gB ? i45 : iA;
                    pk |= (unsigned)idx << (4 * s);
                }
                bpw[(size_t)t * 32] = pk;
            }
            __syncwarp();
            if (lane == 0) atomicAdd(&bp_cnt[c], 1);
        }
    }

    // ================= backtrace tail (wid 0; bp is L2-hot) =================
    __syncthreads();
    if (wid == 0) {
        int* itile = (int*)ring;                 // ring no longer needed
        int b0 = w * 32;
        int cur = slast[lane];
        const unsigned* bprow = g_bp + (size_t)w * NT * 32 + lane;

        unsigned buf[16], nbuf[16];
#pragma unroll
        for (int i = 0; i < 16; i++)
            buf[i] = __ldg(bprow + (size_t)(511 - i) * 32);

        int tb = 511;
        for (int blk = 0; blk < 32; blk += 2) {
            BWD_BLOCK16(buf,  nbuf, 1);              // prefetch always valid
            BWD_BLOCK16(nbuf, buf,  (blk < 30));
        }
        // final step reads bp row 0 (allocated, unused value) — harmless
    }
}

// ---------------------------------------------------------------------------
extern "C" void kernel_launch(void* const* d_in, const int* in_sizes, int n_in,
                              void* d_out, int out_size)
{
    (void)in_sizes; (void)n_in;
    const float* obs  = (const float*)d_in[0];
    const float* tr   = (const float*)d_in[1];
    const float* ini  = (const float*)d_in[2];
    const float* mu   = (const float*)d_in[3];
    const float* lsc  = (const float*)d_in[4];
    float* out = (float*)d_out;

    const int PT = NB * NT;
    int write_path = 0, write_score = 0, score_off = 0;
    if (out_size >= PT + NB)      { write_path = 1; write_score = 1; score_off = PT; }
    else if (out_size >= PT)      { write_path = 1; }
    else                          { write_score = 1; score_off = 0; }

    cudaFuncSetAttribute(k_all, cudaFuncAttributeMaxDynamicSharedMemorySize,
                         RING_BYTES);

    k_all<<<NW, 192, RING_BYTES>>>(obs, tr, ini, mu, lsc, out,
                                   write_path, write_score, score_off);
}

// round 13
// speedup vs baseline: 1.0889x; 1.0889x over previous
#include <cuda_runtime.h>
#include <cstdint>
#include <math.h>

// Problem dims (fixed by the reference setup)
#define NB 4096
#define NT 512
#define NS 6
#define NF 12
#define NW (NB / 32)          // 128 batch-groups

__device__ unsigned g_bp[NW * NT * 32];   // packed backpointers [w][t][lane]

// SMEM geometry: e/v ring (4 chunks) + obs staging (2 buffers)
#define SLICE_W   194                         // padded slice row (words)
#define CHUNK_T   32
#define RING_CH   4
#define CHUNK_W   (CHUNK_T * SLICE_W)         // 6208 words
#define N_CHUNKS  (NT / CHUNK_T)              // 16
#define RING_FLOATS (RING_CH * CHUNK_W)       // 24832
#define STAGE_FLOATS (32 * 32 * 12)           // 12288 per buffer
#define SMEM_FLOATS (RING_FLOATS + 2 * STAGE_FLOATS)
#define SMEM_BYTES  (SMEM_FLOATS * 4)         // 197632 B

// cp.async helpers (LDGSTS; sm_80+)
__device__ __forceinline__ void cp_async16(unsigned dst, const float* src) {
    asm volatile("cp.async.cg.shared.global [%0], [%1], 16;\n"
                 :: "r"(dst), "l"(src));
}
__device__ __forceinline__ void cp_commit() {
    asm volatile("cp.async.commit_group;\n" ::: "memory");
}
template <int N>
__device__ __forceinline__ void cp_wait() {
    asm volatile("cp.async.wait_group %0;\n" :: "n"(N) : "memory");
}

// Issue the cp.async batch for chunk starting at t0 into stage buffer `buf`.
// sites: s = tidP + 96k; site -> (b = s>>5, t = s&31); 3 x 16B per site.
__device__ __forceinline__ void load_chunk(const float* ob, int t0, int buf,
                                           int tidP, unsigned stage_u32)
{
#pragma unroll
    for (int k = 0; k < 11; k++) {
        int s_ = tidP + 96 * k;
        if (s_ < 1024) {
            int b_ = s_ >> 5, tt_ = s_ & 31;
            const float* src = ob + ((size_t)b_ * NT + t0 + tt_) * 12;
            unsigned dst = stage_u32 +
                (unsigned)(buf * STAGE_FLOATS + b_ * 384 + tt_ * 12) * 4u;
            cp_async16(dst,      src);
            cp_async16(dst + 16, src + 4);
            cp_async16(dst + 32, src + 8);
        }
    }
    cp_commit();
}

// One DP step: read e(t) from ring at P, update v in registers, overwrite the
// slice with v_t. Numerical order identical to R6-R11.
#define DP_STEP(P) do {                                                       \
    const float2* q_ = (const float2*)(P);                                    \
    float2 a_ = q_[0], b_ = q_[1], c_ = q_[2];                                \
    float e0=a_.x, e1=a_.y, e2=b_.x, e3=b_.y, e4=c_.x, e5=c_.y;               \
    float n0 = fmaxf(fmaxf(fmaxf(v[0]+lt[0],  v[1]+lt[6]),                    \
                           fmaxf(v[2]+lt[12], v[3]+lt[18])),                  \
                     fmaxf(v[4]+lt[24], v[5]+lt[30])) + e0;                   \
    float n1 = fmaxf(fmaxf(fmaxf(v[0]+lt[1],  v[1]+lt[7]),                    \
                           fmaxf(v[2]+lt[13], v[3]+lt[19])),                  \
                     fmaxf(v[4]+lt[25], v[5]+lt[31])) + e1;                   \
    float n2 = fmaxf(fmaxf(fmaxf(v[0]+lt[2],  v[1]+lt[8]),                    \
                           fmaxf(v[2]+lt[14], v[3]+lt[20])),                  \
                     fmaxf(v[4]+lt[26], v[5]+lt[32])) + e2;                   \
    float n3 = fmaxf(fmaxf(fmaxf(v[0]+lt[3],  v[1]+lt[9]),                    \
                           fmaxf(v[2]+lt[15], v[3]+lt[21])),                  \
                     fmaxf(v[4]+lt[27], v[5]+lt[33])) + e3;                   \
    float n4 = fmaxf(fmaxf(fmaxf(v[0]+lt[4],  v[1]+lt[10]),                   \
                           fmaxf(v[2]+lt[16], v[3]+lt[22])),                  \
                     fmaxf(v[4]+lt[28], v[5]+lt[34])) + e4;                   \
    float n5 = fmaxf(fmaxf(fmaxf(v[0]+lt[5],  v[1]+lt[11]),                   \
                           fmaxf(v[2]+lt[17], v[3]+lt[23])),                  \
                     fmaxf(v[4]+lt[29], v[5]+lt[35])) + e5;                   \
    v[0]=n0; v[1]=n1; v[2]=n2; v[3]=n3; v[4]=n4; v[5]=n5;                     \
    float2* d_ = (float2*)(P);                                                \
    d_[0] = make_float2(v[0], v[1]);                                          \
    d_[1] = make_float2(v[2], v[3]);                                          \
    d_[2] = make_float2(v[4], v[5]); } while (0)

// Backtrace 16-step block (ping-pong register buffers, compile-time indices)
#define BWD_BLOCK16(CUR, NXT, DO_PREF)                                      \
do {                                                                        \
    _Pragma("unroll")                                                       \
    for (int i = 0; i < 16; i++) {                                          \
        if (DO_PREF) NXT[i] = __ldg(bprow + (size_t)(tb - 16 - i) * 32);    \
        itile[lane * 33 + ((tb - i) & 31)] = cur;    /* path[tb - i] */     \
        cur = (CUR[i] >> (cur * 4)) & 7;             /* path[tb - i - 1] */ \
    }                                                                       \
    if (((tb - 15) & 31) == 0) {                                            \
        __syncwarp();                                                       \
        if (write_path) {                                                   \
            _Pragma("unroll 8")                                             \
            for (int r = 0; r < 32; r++)                                    \
                out[(size_t)(b0 + r) * NT + (tb - 15) + lane] =             \
                    (float)itile[r * 33 + lane];                            \
        }                                                                   \
        __syncwarp();                                                       \
    }                                                                       \
    tb -= 16;                                                               \
} while (0)

// ---------------------------------------------------------------------------
// THE kernel. 192 threads (6 warps) per batch-group:
//   init:    all threads compute params (softmax logs, emission consts) in SMEM
//   wid 0-2: producers — cp.async a whole 48KB obs chunk into a double-
//            buffered SMEM stage (huge MLP, zero register payload), then
//            compute emission logp stage -> ring slot
//   wid 3:   serial DP consumer (writes v_t into the ring in place)
//   wid 4-5: bp workers; read v from ring, write packed bp to gmem
//   tail:    after __syncthreads(), wid 0 runs the backtrace (bp is L2-hot)
// Ring depth 4: producer writes chunk c over chunk c-4; bp chunk c-3 is the
// last reader of chunk c-4's slices, so the producer waits bp_cnt[c-3] >= 2.
// ---------------------------------------------------------------------------
__global__ void __launch_bounds__(192, 1)
k_all(const float* __restrict__ obs,
      const float* __restrict__ trans,
      const float* __restrict__ init,
      const float* __restrict__ means,
      const float* __restrict__ logsc,
      float* __restrict__ out,
      int write_path, int write_score, int score_off)
{
    extern __shared__ float smem[];
    float* ring  = smem;                       // [RING_CH][CHUNK_W]
    float* stage = smem + RING_FLOATS;         // [2][32*32*12]  (b*384 + t*12 + f)
    __shared__ float sp[156];
    __shared__ float slt[36];
    __shared__ float sloginit[6];
    __shared__ int   prod_cnt[N_CHUNKS];
    __shared__ int   bp_cnt[N_CHUNKS];
    __shared__ int   cons_flag;
    __shared__ int   slast[32];

    int tid  = threadIdx.x;
    int lane = tid & 31;
    int wid  = tid >> 5;
    int w    = blockIdx.x;

    // ---- parameter setup in SMEM ----
    if (tid < 36) {
        int p = tid / 6, s = tid - p * 6;
        float m = trans[p * 6 + 0];
#pragma unroll
        for (int k = 1; k < 6; k++) m = fmaxf(m, trans[p * 6 + k]);
        float sum = 0.f;
#pragma unroll
        for (int k = 0; k < 6; k++) sum += expf(trans[p * 6 + k] - m);
        slt[tid] = logf(expf(trans[p * 6 + s] - m) / sum + 1e-8f);
    }
    if (tid >= 36 && tid < 42) {
        int s = tid - 36;
        float m = init[0];
#pragma unroll
        for (int k = 1; k < 6; k++) m = fmaxf(m, init[k]);
        float sum = 0.f;
#pragma unroll
        for (int k = 0; k < 6; k++) sum += expf(init[k] - m);
        sloginit[s] = logf(expf(init[s] - m) / sum + 1e-8f);
    }
    if (tid >= 64 && tid < 136) {
        int idx = tid - 64;
        int s = idx / 12, f = idx - s * 12;
        float x    = logsc[s * 12 + f];
        float sc   = log1pf(expf(x)) + 1e-6f;
        float den  = sc + 1e-6f;
        float inv2 = 1.0f / (den * den);
        float mu   = means[s * 12 + f];
        sp[s * 12 + f]      = inv2;
        sp[72 + s * 12 + f] = mu * inv2;
    }
    if (tid >= 136 && tid < 142) {
        int s = tid - 136;
        float c = 0.f, ld = 0.f;
#pragma unroll
        for (int f = 0; f < 12; f++) {
            float x    = logsc[s * 12 + f];
            float sc   = log1pf(expf(x)) + 1e-6f;
            float den  = sc + 1e-6f;
            float inv2 = 1.0f / (den * den);
            float mu   = means[s * 12 + f];
            c  += mu * mu * inv2;
            ld += logf(sc);
        }
        sp[144 + s] = c;
        sp[150 + s] = ld;
    }
    if (tid < N_CHUNKS) { prod_cnt[tid] = 0; bp_cnt[tid] = 0; }
    if (tid == 0) cons_flag = 0;
    __syncthreads();

    if (wid < 3) {
        // ================= producers (cp.async staged) =================
        const float* ob = obs + (size_t)w * 32 * NT * NF;
        int tidP = wid * 32 + lane;            // 0..95
        unsigned stage_u32 = (unsigned)__cvta_generic_to_shared(stage);

        load_chunk(ob, 0, 0, tidP, stage_u32);

#pragma unroll 1
        for (int c = 0; c < N_CHUNKS; c++) {
            if (c < N_CHUNKS - 1) {
                load_chunk(ob, (c + 1) * CHUNK_T, (c + 1) & 1, tidP, stage_u32);
                cp_wait<1>();
            } else {
                cp_wait<0>();
            }

            if (c >= RING_CH) {   // slot (c&3) free iff bp chunk c-3 done
                while (*(volatile int*)&bp_cnt[c - (RING_CH - 1)] < 2) { }
                __threadfence_block();
            }
            float* slot = ring + (size_t)(c & (RING_CH - 1)) * CHUNK_W;
            const float* stg = stage + (size_t)(c & 1) * STAGE_FLOATS;

#pragma unroll
            for (int k = 0; k < 11; k++) {
                int s_ = tidP + 96 * k;
                if (s_ < 1024) {
                    int b_ = s_ >> 5, tt_ = s_ & 31;
                    const float4* op = (const float4*)(stg + b_ * 384 + tt_ * 12);
                    float4 q0 = op[0], q1 = op[1], q2 = op[2];
                    float o[12] = { q0.x, q0.y, q0.z, q0.w, q1.x, q1.y, q1.z, q1.w,
                                    q2.x, q2.y, q2.z, q2.w };
                    float osq[12];
#pragma unroll
                    for (int f = 0; f < 12; f++) osq[f] = o[f] * o[f];
                    float e[6];
#pragma unroll
                    for (int s = 0; s < NS; s++) {
                        float a1 = 0.f, a2 = 0.f;
#pragma unroll
                        for (int f = 0; f < 12; f++) {
                            a1 = fmaf(osq[f], sp[s * 12 + f], a1);
                            a2 = fmaf(o[f],   sp[72 + s * 12 + f], a2);
                        }
                        e[s] = -0.5f * (a1 - 2.f * a2 + sp[144 + s]) - sp[150 + s];
                    }
                    float2* d = (float2*)(slot + tt_ * SLICE_W + b_ * 6);
                    d[0] = make_float2(e[0], e[1]);
                    d[1] = make_float2(e[2], e[3]);
                    d[2] = make_float2(e[4], e[5]);
                }
            }
            __syncwarp();
            __threadfence_block();
            if (lane == 0) atomicAdd(&prod_cnt[c], 1);
        }
    } else if (wid == 3) {
        // ================= consumer (chunk DP, unroll-4 groups) ============
        float lt[36];
#pragma unroll
        for (int i = 0; i < 36; i++) lt[i] = slt[i];

        float v[6];

        while (*(volatile int*)&prod_cnt[0] < 3) { }
        __threadfence_block();
        {
            float* bb = ring + lane * 6;
            const float2* q = (const float2*)bb;
            float2 a = q[0], b2 = q[1], c2 = q[2];
            v[0] = sloginit[0] + a.x;  v[1] = sloginit[1] + a.y;
            v[2] = sloginit[2] + b2.x; v[3] = sloginit[3] + b2.y;
            v[4] = sloginit[4] + c2.x; v[5] = sloginit[5] + c2.y;
            float2* d = (float2*)bb;
            d[0] = make_float2(v[0], v[1]);
            d[1] = make_float2(v[2], v[3]);
            d[2] = make_float2(v[4], v[5]);
            DP_STEP(bb + 1 * SLICE_W);
            DP_STEP(bb + 2 * SLICE_W);
            DP_STEP(bb + 3 * SLICE_W);
#pragma unroll 1
            for (int g = 1; g < 8; g++) {
                float* p4 = bb + g * 4 * SLICE_W;
                DP_STEP(p4);
                DP_STEP(p4 + SLICE_W);
                DP_STEP(p4 + 2 * SLICE_W);
                DP_STEP(p4 + 3 * SLICE_W);
            }
        }
        __syncwarp();
        __threadfence_block();
        if (lane == 0) *(volatile int*)&cons_flag = 1;

#pragma unroll 1
        for (int c = 1; c < N_CHUNKS; c++) {
            while (*(volatile int*)&prod_cnt[c] < 3) { }
            __threadfence_block();
            float* bb = ring + (size_t)(c & (RING_CH - 1)) * CHUNK_W + lane * 6;
#pragma unroll 1
            for (int g = 0; g < 8; g++) {
                float* p4 = bb + g * 4 * SLICE_W;
                DP_STEP(p4);
                DP_STEP(p4 + SLICE_W);
                DP_STEP(p4 + 2 * SLICE_W);
                DP_STEP(p4 + 3 * SLICE_W);
            }
            __syncwarp();
            __threadfence_block();
            if (lane == 0) *(volatile int*)&cons_flag = c + 1;
        }

        float m = v[0]; int idx = 0;
#pragma unroll
        for (int s = 1; s < 6; s++) if (v[s] > m) { m = v[s]; idx = s; }
        slast[lane] = idx;
        if (write_score) out[score_off + w * 32 + lane] = m;
    } else {
        // ================= bp workers (wid 4: slices 0-15, wid 5: 16-31) ===
        float lt[36];
#pragma unroll
        for (int i = 0; i < 36; i++) lt[i] = slt[i];

        int half = wid - 4;
        unsigned* bpw = g_bp + (size_t)w * NT * 32 + lane;

#pragma unroll 1
        for (int c = 0; c < N_CHUNKS; c++) {
            while (*(volatile int*)&cons_flag < c + 1) { }
            __threadfence_block();

#pragma unroll 1
            for (int i = 0; i < 16; i++) {
                int t = c * 32 + half * 16 + i;
                if (t == 0) continue;
                int tp = t - 1;
                const float2* q = (const float2*)(ring +
                    (size_t)((tp >> 5) & (RING_CH - 1)) * CHUNK_W +
                    (tp & 31) * SLICE_W + lane * 6);
                float2 a = q[0], bq = q[1], cc = q[2];
                float v0 = a.x, v1 = a.y, v2 = bq.x, v3 = bq.y, v4 = cc.x, v5 = cc.y;

                unsigned pk = 0;
#pragma unroll
                for (int s = 0; s < 6; s++) {
                    float c0 = v0 + lt[s],      c1 = v1 + lt[6 + s],  c2 = v2 + lt[12 + s];
                    float c3 = v3 + lt[18 + s], c4 = v4 + lt[24 + s], c5 = v5 + lt[30 + s];
                    bool g01 = c1 > c0;  float m01 = g01 ? c1 : c0;  int i01 = g01 ? 1 : 0;
                    bool g23 = c3 > c2;  float m23 = g23 ? c3 : c2;  int i23 = g23 ? 3 : 2;
                    bool g45 = c5 > c4;  float m45 = g45 ? c5 : c4;  int i45 = g45 ? 5 : 4;
                    bool gA  = m23 > m01; float mA = gA ? m23 : m01; int iA = gA ? i23 : i01;
                    bool gB  = m45 > mA;  int idx = gB ? i45 : iA;
                    pk |= (unsigned)idx << (4 * s);
                }
                bpw[(size_t)t * 32] = pk;
            }
            __syncwarp();
            if (lane == 0) atomicAdd(&bp_cnt[c], 1);
        }
    }

    // ================= backtrace tail (wid 0; bp is L2-hot) =================
    __syncthreads();
    if (wid == 0) {
        int* itile = (int*)smem;                 // smem no longer needed
        int b0 = w * 32;
        int cur = slast[lane];
        const unsigned* bprow = g_bp + (size_t)w * NT * 32 + lane;

        unsigned buf[16], nbuf[16];
#pragma unroll
        for (int i = 0; i < 16; i++)
            buf[i] = __ldg(bprow + (size_t)(511 - i) * 32);

        int tb = 511;
        for (int blk = 0; blk < 32; blk += 2) {
            BWD_BLOCK16(buf,  nbuf, 1);
            BWD_BLOCK16(nbuf, buf,  (blk < 30));
        }
        // final step reads bp row 0 (allocated, unused value) — harmless
    }
}

// ---------------------------------------------------------------------------
extern "C" void kernel_launch(void* const* d_in, const int* in_sizes, int n_in,
                              void* d_out, int out_size)
{
    (void)in_sizes; (void)n_in;
    const float* obs  = (const float*)d_in[0];
    const float* tr   = (const float*)d_in[1];
    const float* ini  = (const float*)d_in[2];
    const float* mu   = (const float*)d_in[3];
    const float* lsc  = (const float*)d_in[4];
    float* out = (float*)d_out;

    const int PT = NB * NT;
    int write_path = 0, write_score = 0, score_off = 0;
    if (out_size >= PT + NB)      { write_path = 1; write_score = 1; score_off = PT; }
    else if (out_size >= PT)      { write_path = 1; }
    else                          { write_score = 1; score_off = 0; }

    cudaFuncSetAttribute(k_all, cudaFuncAttributeMaxDynamicSharedMemorySize,
                         SMEM_BYTES);

    k_all<<<NW, 192, SMEM_BYTES>>>(obs, tr, ini, mu, lsc, out,
                                   write_path, write_score, score_off);
}

// round 14
// speedup vs baseline: 1.1141x; 1.0231x over previous
#include <cuda_runtime.h>
#include <cstdint>
#include <math.h>

// Problem dims (fixed by the reference setup)
#define NB 4096
#define NT 512
#define NS 6
#define NF 12
#define NW (NB / 32)          // 128 batch-groups

__device__ unsigned g_bp[NW * NT * 32];   // packed backpointers [w][t][lane]

// SMEM geometry: e/v ring (4 chunks) + obs staging (2 buffers)
#define SLICE_W   194                         // padded slice row (words)
#define CHUNK_T   32
#define RING_CH   4
#define CHUNK_W   (CHUNK_T * SLICE_W)         // 6208 words
#define N_CHUNKS  (NT / CHUNK_T)              // 16
#define RING_FLOATS (RING_CH * CHUNK_W)       // 24832
#define STAGE_FLOATS (32 * 32 * 12)           // 12288 per buffer
#define SMEM_FLOATS (RING_FLOATS + 2 * STAGE_FLOATS)
#define SMEM_BYTES  (SMEM_FLOATS * 4)         // 197632 B

// cp.async helpers (LDGSTS; sm_80+)
__device__ __forceinline__ void cp_async16(unsigned dst, const float* src) {
    asm volatile("cp.async.cg.shared.global [%0], [%1], 16;\n"
                 :: "r"(dst), "l"(src));
}
__device__ __forceinline__ void cp_commit() {
    asm volatile("cp.async.commit_group;\n" ::: "memory");
}
template <int N>
__device__ __forceinline__ void cp_wait() {
    asm volatile("cp.async.wait_group %0;\n" :: "n"(N) : "memory");
}

// Issue the cp.async batch for chunk starting at t0 into stage buffer `buf`.
__device__ __forceinline__ void load_chunk(const float* ob, int t0, int buf,
                                           int tidP, unsigned stage_u32)
{
#pragma unroll
    for (int k = 0; k < 11; k++) {
        int s_ = tidP + 96 * k;
        if (s_ < 1024) {
            int b_ = s_ >> 5, tt_ = s_ & 31;
            const float* src = ob + ((size_t)b_ * NT + t0 + tt_) * 12;
            unsigned dst = stage_u32 +
                (unsigned)(buf * STAGE_FLOATS + b_ * 384 + tt_ * 12) * 4u;
            cp_async16(dst,      src);
            cp_async16(dst + 16, src + 4);
            cp_async16(dst + 32, src + 8);
        }
    }
    cp_commit();
}

// Consumer DP step (2 lanes per batch; lane parity h owns states h*3..h*3+2).
// Exact same add/max tree order per state as all prior rounds; partner's
// values arrive via shfl (bitwise exact).
#define CSTEP(PTR) do {                                                      \
    const float* sl_ = (PTR);                                                \
    float e0_ = sl_[0], e1_ = sl_[1], e2_ = sl_[2];                          \
    float n0_ = fmaxf(fmaxf(fmaxf(v[0]+ltl[0],  v[1]+ltl[3]),                \
                            fmaxf(v[2]+ltl[6],  v[3]+ltl[9])),               \
                      fmaxf(v[4]+ltl[12], v[5]+ltl[15])) + e0_;              \
    float n1_ = fmaxf(fmaxf(fmaxf(v[0]+ltl[1],  v[1]+ltl[4]),                \
                            fmaxf(v[2]+ltl[7],  v[3]+ltl[10])),              \
                      fmaxf(v[4]+ltl[13], v[5]+ltl[16])) + e1_;              \
    float n2_ = fmaxf(fmaxf(fmaxf(v[0]+ltl[2],  v[1]+ltl[5]),                \
                            fmaxf(v[2]+ltl[8],  v[3]+ltl[11])),              \
                      fmaxf(v[4]+ltl[14], v[5]+ltl[17])) + e2_;              \
    float* sw_ = (float*)(PTR);                                              \
    sw_[0] = n0_; sw_[1] = n1_; sw_[2] = n2_;                                \
    float r0_ = __shfl_xor_sync(0xffffffffu, n0_, 1);                        \
    float r1_ = __shfl_xor_sync(0xffffffffu, n1_, 1);                        \
    float r2_ = __shfl_xor_sync(0xffffffffu, n2_, 1);                        \
    v[0] = h ? r0_ : n0_;  v[1] = h ? r1_ : n1_;  v[2] = h ? r2_ : n2_;      \
    v[3] = h ? n0_ : r0_;  v[4] = h ? n1_ : r1_;  v[5] = h ? n2_ : r2_;      \
} while (0)

// Backtrace 16-step block (ping-pong register buffers, compile-time indices)
#define BWD_BLOCK16(CUR, NXT, DO_PREF)                                      \
do {                                                                        \
    _Pragma("unroll")                                                       \
    for (int i = 0; i < 16; i++) {                                          \
        if (DO_PREF) NXT[i] = __ldg(bprow + (size_t)(tb - 16 - i) * 32);    \
        itile[lane * 33 + ((tb - i) & 31)] = cur;    /* path[tb - i] */     \
        cur = (CUR[i] >> (cur * 4)) & 7;             /* path[tb - i - 1] */ \
    }                                                                       \
    if (((tb - 15) & 31) == 0) {                                            \
        __syncwarp();                                                       \
        if (write_path) {                                                   \
            _Pragma("unroll 8")                                             \
            for (int r = 0; r < 32; r++)                                    \
                out[(size_t)(b0 + r) * NT + (tb - 15) + lane] =             \
                    (float)itile[r * 33 + lane];                            \
        }                                                                   \
        __syncwarp();                                                       \
    }                                                                       \
    tb -= 16;                                                               \
} while (0)

// ---------------------------------------------------------------------------
// THE kernel. 256 threads (8 warps) per batch-group:
//   wid 0-2: producers — cp.async staged obs; emission via packed fma.rn.f32x2
//   wid 3,4: consumers — 2 lanes/batch DP (wid3: batches 0-15, wid4: 16-31)
//   wid 5-7: bp workers (3-way split of each chunk)
//   tail:    wid 0 backtrace after __syncthreads()
// SMSP map (wid&3): prod {0,1,2}, cons {3,0}, bp {1,2,3} — balanced.
// Ring depth 4: slot (c&3) reusable iff bp chunk c-3 done (bp_cnt >= 3).
// ---------------------------------------------------------------------------
__global__ void __launch_bounds__(256, 1)
k_all(const float* __restrict__ obs,
      const float* __restrict__ trans,
      const float* __restrict__ init,
      const float* __restrict__ means,
      const float* __restrict__ logsc,
      float* __restrict__ out,
      int write_path, int write_score, int score_off)
{
    extern __shared__ float smem[];
    float* ring  = smem;                       // [RING_CH][CHUNK_W]
    float* stage = smem + RING_FLOATS;         // [2][32*32*12]  (b*384 + t*12 + f)
    __shared__ float2 sp2[72];                 // (inv2, mu*inv2) per (s,f)
    __shared__ float  spc[6], spl[6];          // c[s], logdet[s]
    __shared__ float  slt[36];                 // log-transition [p][s]
    __shared__ float  sloginit[6];
    __shared__ int    prod_cnt[N_CHUNKS];
    __shared__ int    cons_cnt[N_CHUNKS];
    __shared__ int    bp_cnt[N_CHUNKS];
    __shared__ int    slast[32];

    int tid  = threadIdx.x;
    int lane = tid & 31;
    int wid  = tid >> 5;
    int w    = blockIdx.x;

    // ---- parameter setup in SMEM ----
    if (tid < 36) {
        int p = tid / 6, s = tid - p * 6;
        float m = trans[p * 6 + 0];
#pragma unroll
        for (int k = 1; k < 6; k++) m = fmaxf(m, trans[p * 6 + k]);
        float sum = 0.f;
#pragma unroll
        for (int k = 0; k < 6; k++) sum += expf(trans[p * 6 + k] - m);
        slt[tid] = logf(expf(trans[p * 6 + s] - m) / sum + 1e-8f);
    }
    if (tid >= 36 && tid < 42) {
        int s = tid - 36;
        float m = init[0];
#pragma unroll
        for (int k = 1; k < 6; k++) m = fmaxf(m, init[k]);
        float sum = 0.f;
#pragma unroll
        for (int k = 0; k < 6; k++) sum += expf(init[k] - m);
        sloginit[s] = logf(expf(init[s] - m) / sum + 1e-8f);
    }
    if (tid >= 64 && tid < 136) {
        int idx = tid - 64;
        int s = idx / 12, f = idx - s * 12;
        float x    = logsc[s * 12 + f];
        float sc   = log1pf(expf(x)) + 1e-6f;
        float den  = sc + 1e-6f;
        float inv2 = 1.0f / (den * den);
        float mu   = means[s * 12 + f];
        sp2[s * 12 + f] = make_float2(inv2, mu * inv2);
    }
    if (tid >= 136 && tid < 142) {
        int s = tid - 136;
        float c = 0.f, ld = 0.f;
#pragma unroll
        for (int f = 0; f < 12; f++) {
            float x    = logsc[s * 12 + f];
            float sc   = log1pf(expf(x)) + 1e-6f;
            float den  = sc + 1e-6f;
            float inv2 = 1.0f / (den * den);
            float mu   = means[s * 12 + f];
            c  += mu * mu * inv2;
            ld += logf(sc);
        }
        spc[s] = c;
        spl[s] = ld;
    }
    if (tid < N_CHUNKS) { prod_cnt[tid] = 0; cons_cnt[tid] = 0; bp_cnt[tid] = 0; }
    __syncthreads();

    if (wid < 3) {
        // ================= producers (cp.async + packed f32x2 FMA) ========
        const float* ob = obs + (size_t)w * 32 * NT * NF;
        int tidP = wid * 32 + lane;            // 0..95
        unsigned stage_u32 = (unsigned)__cvta_generic_to_shared(stage);

        load_chunk(ob, 0, 0, tidP, stage_u32);

#pragma unroll 1
        for (int c = 0; c < N_CHUNKS; c++) {
            if (c < N_CHUNKS - 1) {
                load_chunk(ob, (c + 1) * CHUNK_T, (c + 1) & 1, tidP, stage_u32);
                cp_wait<1>();
            } else {
                cp_wait<0>();
            }

            if (c >= RING_CH) {   // slot (c&3) free iff bp chunk c-3 done
                while (*(volatile int*)&bp_cnt[c - (RING_CH - 1)] < 3) { }
                __threadfence_block();
            }
            float* slot = ring + (size_t)(c & (RING_CH - 1)) * CHUNK_W;
            const float* stg = stage + (size_t)(c & 1) * STAGE_FLOATS;

#pragma unroll
            for (int k = 0; k < 11; k++) {
                int s_ = tidP + 96 * k;
                if (s_ < 1024) {
                    int b_ = s_ >> 5, tt_ = s_ & 31;
                    const float4* op = (const float4*)(stg + b_ * 384 + tt_ * 12);
                    float4 q0 = op[0], q1 = op[1], q2 = op[2];
                    float o[12] = { q0.x, q0.y, q0.z, q0.w, q1.x, q1.y, q1.z, q1.w,
                                    q2.x, q2.y, q2.z, q2.w };
                    // packed (osq, o) operands
                    unsigned long long po[12];
#pragma unroll
                    for (int f = 0; f < 12; f++) {
                        float osq = o[f] * o[f];
                        asm("mov.b64 %0, {%1, %2};"
                            : "=l"(po[f]) : "f"(osq), "f"(o[f]));
                    }
                    float e[6];
#pragma unroll
                    for (int s = 0; s < NS; s++) {
                        unsigned long long acc = 0ULL;   // (0.0f, 0.0f)
#pragma unroll
                        for (int f = 0; f < 12; f++) {
                            unsigned long long pp =
                                *(const unsigned long long*)&sp2[s * 12 + f];
                            asm("fma.rn.f32x2 %0, %1, %2, %3;"
                                : "=l"(acc) : "l"(po[f]), "l"(pp), "l"(acc));
                        }
                        float a1, a2;
                        asm("mov.b64 {%0, %1}, %2;"
                            : "=f"(a1), "=f"(a2) : "l"(acc));
                        e[s] = -0.5f * (a1 - 2.f * a2 + spc[s]) - spl[s];
                    }
                    float2* d = (float2*)(slot + tt_ * SLICE_W + b_ * 6);
                    d[0] = make_float2(e[0], e[1]);
                    d[1] = make_float2(e[2], e[3]);
                    d[2] = make_float2(e[4], e[5]);
                }
            }
            __syncwarp();
            __threadfence_block();
            if (lane == 0) atomicAdd(&prod_cnt[c], 1);
        }
    } else if (wid == 3 || wid == 4) {
        // ================= consumers (2 lanes / batch) =====================
        int h   = lane & 1;                    // state-half owned by this lane
        int bb_ = (wid == 3 ? 0 : 16) + (lane >> 1);   // batch 0..31
        float ltl[18];                         // ltl[p*3+j] = lt[p][h*3+j]
#pragma unroll
        for (int p = 0; p < 6; p++)
#pragma unroll
            for (int j = 0; j < 3; j++)
                ltl[p * 3 + j] = slt[p * 6 + h * 3 + j];

        float v[6];
        int soff = bb_ * 6 + h * 3;

        // chunk 0: t=0 init + steps 1..31
        while (*(volatile int*)&prod_cnt[0] < 3) { }
        __threadfence_block();
        {
            float* sl = ring + soff;
            float n0 = sloginit[h * 3 + 0] + sl[0];
            float n1 = sloginit[h * 3 + 1] + sl[1];
            float n2 = sloginit[h * 3 + 2] + sl[2];
            sl[0] = n0; sl[1] = n1; sl[2] = n2;
            float r0 = __shfl_xor_sync(0xffffffffu, n0, 1);
            float r1 = __shfl_xor_sync(0xffffffffu, n1, 1);
            float r2 = __shfl_xor_sync(0xffffffffu, n2, 1);
            v[0] = h ? r0 : n0;  v[1] = h ? r1 : n1;  v[2] = h ? r2 : n2;
            v[3] = h ? n0 : r0;  v[4] = h ? n1 : r1;  v[5] = h ? n2 : r2;
#pragma unroll 4
            for (int i = 1; i < 32; i++) CSTEP(ring + i * SLICE_W + soff);
        }
        __syncwarp();
        __threadfence_block();
        if (lane == 0) atomicAdd(&cons_cnt[0], 1);

#pragma unroll 1
        for (int c = 1; c < N_CHUNKS; c++) {
            while (*(volatile int*)&prod_cnt[c] < 3) { }
            __threadfence_block();
            float* bb = ring + (size_t)(c & (RING_CH - 1)) * CHUNK_W + soff;
#pragma unroll 4
            for (int i = 0; i < 32; i++) CSTEP(bb + i * SLICE_W);
            __syncwarp();
            __threadfence_block();
            if (lane == 0) atomicAdd(&cons_cnt[c], 1);
        }

        // final state / score (first-argmax, strict >) — even lane writes
        if (h == 0) {
            float m = v[0]; int idx = 0;
#pragma unroll
            for (int s = 1; s < 6; s++) if (v[s] > m) { m = v[s]; idx = s; }
            slast[bb_] = idx;
            if (write_score) out[score_off + w * 32 + bb_] = m;
        }
    } else {
        // ================= bp workers (3-way split per chunk) ==============
        float lt[36];
#pragma unroll
        for (int i = 0; i < 36; i++) lt[i] = slt[i];

        int j  = wid - 5;                       // 0,1,2
        int i0 = (j == 0) ? 0 : (j == 1 ? 11 : 22);
        int i1 = (j == 0) ? 11 : (j == 1 ? 22 : 32);
        unsigned* bpw = g_bp + (size_t)w * NT * 32 + lane;

#pragma unroll 1
        for (int c = 0; c < N_CHUNKS; c++) {
            while (*(volatile int*)&cons_cnt[c] < 2) { }
            __threadfence_block();

#pragma unroll 1
            for (int i = i0; i < i1; i++) {
                int t = c * 32 + i;
                if (t == 0) continue;
                int tp = t - 1;
                const float2* q = (const float2*)(ring +
                    (size_t)((tp >> 5) & (RING_CH - 1)) * CHUNK_W +
                    (tp & 31) * SLICE_W + lane * 6);
                float2 a = q[0], bq = q[1], cc = q[2];
                float v0 = a.x, v1 = a.y, v2 = bq.x, v3 = bq.y, v4 = cc.x, v5 = cc.y;

                unsigned pk = 0;
#pragma unroll
                for (int s = 0; s < 6; s++) {
                    float c0 = v0 + lt[s],      c1 = v1 + lt[6 + s],  c2 = v2 + lt[12 + s];
                    float c3 = v3 + lt[18 + s], c4 = v4 + lt[24 + s], c5 = v5 + lt[30 + s];
                    bool g01 = c1 > c0;  float m01 = g01 ? c1 : c0;  int i01 = g01 ? 1 : 0;
                    bool g23 = c3 > c2;  float m23 = g23 ? c3 : c2;  int i23 = g23 ? 3 : 2;
                    bool g45 = c5 > c4;  float m45 = g45 ? c5 : c4;  int i45 = g45 ? 5 : 4;
                    bool gA  = m23 > m01; float mA = gA ? m23 : m01; int iA = gA ? i23 : i01;
                    bool gB  = m45 > mA;  int idx = gB ? i45 : iA;
                    pk |= (unsigned)idx << (4 * s);
                }
                bpw[(size_t)t * 32] = pk;
            }
            __syncwarp();
            if (lane == 0) atomicAdd(&bp_cnt[c], 1);
        }
    }

    // ================= backtrace tail (wid 0; bp is L2-hot) =================
    __syncthreads();
    if (wid == 0) {
        int* itile = (int*)smem;                 // smem no longer needed
        int b0 = w * 32;
        int cur = slast[lane];
        const unsigned* bprow = g_bp + (size_t)w * NT * 32 + lane;

        unsigned buf[16], nbuf[16];
#pragma unroll
        for (int i = 0; i < 16; i++)
            buf[i] = __ldg(bprow + (size_t)(511 - i) * 32);

        int tb = 511;
        for (int blk = 0; blk < 32; blk += 2) {
            BWD_BLOCK16(buf,  nbuf, 1);
            BWD_BLOCK16(nbuf, buf,  (blk < 30));
        }
        // final step reads bp row 0 (allocated, unused value) — harmless
    }
}

// ---------------------------------------------------------------------------
extern "C" void kernel_launch(void* const* d_in, const int* in_sizes, int n_in,
                              void* d_out, int out_size)
{
    (void)in_sizes; (void)n_in;
    const float* obs  = (const float*)d_in[0];
    const float* tr   = (const float*)d_in[1];
    const float* ini  = (const float*)d_in[2];
    const float* mu   = (const float*)d_in[3];
    const float* lsc  = (const float*)d_in[4];
    float* out = (float*)d_out;

    const int PT = NB * NT;
    int write_path = 0, write_score = 0, score_off = 0;
    if (out_size >= PT + NB)      { write_path = 1; write_score = 1; score_off = PT; }
    else if (out_size >= PT)      { write_path = 1; }
    else                          { write_score = 1; score_off = 0; }

    cudaFuncSetAttribute(k_all, cudaFuncAttributeMaxDynamicSharedMemorySize,
                         SMEM_BYTES);

    k_all<<<NW, 256, SMEM_BYTES>>>(obs, tr, ini, mu, lsc, out,
                                   write_path, write_score, score_off);
}